// round 16
// baseline (speedup 1.0000x reference)
#include <cuda_runtime.h>
#include <cuda_bf16.h>
#include <cstdint>
#include <math.h>

#define B_ 512
#define S_ 200
#define H_ 512
#define A_ 32
#define M_ (B_*S_)          // 102400 rows
#define NEGV (-1e9f)

// ---------------- device scratch (no allocations allowed) ----------------
__device__ float g_moe[(M_ + 64) * H_];       // ~210MB
__device__ __nv_bfloat16 g_A0h[M_ * H_];      // bf16 hi of (item+pos)
__device__ __nv_bfloat16 g_A0l[M_ * H_];      // bf16 lo residual
__device__ __nv_bfloat16 g_A1h[M_ * H_];      // bf16 hi of item (2-term: no lo)
__device__ float g_w[M_];
__device__ float g_bij[M_ * A_];
__device__ float g_cijt[M_ * A_];
__device__ float g_awT4[H_ * A_];             // aspect_w: [(k>>2)*32+a]*4+(k&3)
__device__ __nv_bfloat16 g_wThi[H_ * H_];     // W^T hi [n][k]
__device__ __nv_bfloat16 g_wTlo[H_ * H_];     // W^T lo
__device__ int   g_count[B_ * A_];
__device__ float g_dummy_gates[M_ * A_];
__device__ float g_dummy_mask[B_ * A_];

// ---------------- PTX helpers (family-portable) ----------------
__device__ __forceinline__ uint32_t smem_u32(const void* p) {
    uint32_t a;
    asm("{ .reg .u64 t; cvta.to.shared.u64 t, %1; cvt.u32.u64 %0, t; }" : "=r"(a) : "l"(p));
    return a;
}
__device__ __forceinline__ void ldm4(uint32_t r[4], uint32_t addr) {
    asm volatile("ldmatrix.sync.aligned.m8n8.x4.shared.b16 {%0,%1,%2,%3}, [%4];"
                 : "=r"(r[0]), "=r"(r[1]), "=r"(r[2]), "=r"(r[3]) : "r"(addr));
}
__device__ __forceinline__ void mma_bf16(float c[4], const uint32_t a[4],
                                         uint32_t b0, uint32_t b1) {
    asm volatile(
        "mma.sync.aligned.m16n8k16.row.col.f32.bf16.bf16.f32 "
        "{%0,%1,%2,%3},{%4,%5,%6,%7},{%8,%9},{%0,%1,%2,%3};"
        : "+f"(c[0]), "+f"(c[1]), "+f"(c[2]), "+f"(c[3])
        : "r"(a[0]), "r"(a[1]), "r"(a[2]), "r"(a[3]), "r"(b0), "r"(b1));
}
__device__ __forceinline__ void mma_tf32(float c[4],
                                         uint32_t a0, uint32_t a1, uint32_t a2, uint32_t a3,
                                         uint32_t b0, uint32_t b1) {
    asm volatile(
        "mma.sync.aligned.m16n8k8.row.col.f32.tf32.tf32.f32 "
        "{%0,%1,%2,%3},{%4,%5,%6,%7},{%8,%9},{%0,%1,%2,%3};"
        : "+f"(c[0]), "+f"(c[1]), "+f"(c[2]), "+f"(c[3])
        : "r"(a0), "r"(a1), "r"(a2), "r"(a3), "r"(b0), "r"(b1));
}
__device__ __forceinline__ uint32_t f2tf32(float x) {
    uint32_t y;
    asm("cvt.rna.tf32.f32 %0, %1;" : "=r"(y) : "f"(x));
    return y;
}
__device__ __forceinline__ void split_pk(float x, float y, uint32_t& hi, uint32_t& lo) {
    __nv_bfloat162 h = __float22bfloat162_rn(make_float2(x, y));
    float hx = __bfloat162float(h.x), hy = __bfloat162float(h.y);
    __nv_bfloat162 l = __float22bfloat162_rn(make_float2(x - hx, y - hy));
    hi = *(uint32_t*)&h;
    lo = *(uint32_t*)&l;
}
__device__ __forceinline__ uint32_t pk_bf16x2(float x, float y) {
    __nv_bfloat162 t = __float22bfloat162_rn(make_float2(x, y));
    return *(uint32_t*)&t;
}
#define CP_ASYNC16(dst, src) \
    asm volatile("cp.async.cg.shared.global [%0], [%1], 16;" :: "r"(dst), "l"(src))
#define CP_COMMIT() asm volatile("cp.async.commit_group;" ::: "memory")
#define CP_WAIT2()  asm volatile("cp.async.wait_group 2;" ::: "memory")
#define CP_WAIT1()  asm volatile("cp.async.wait_group 1;" ::: "memory")
#define SWZ(off) ((off) ^ (((off) >> 3) & 0x70))

// ---------------- init ----------------
__global__ void zero_kernel() {
    int i = blockIdx.x * blockDim.x + threadIdx.x;
    if (i < M_) g_w[i] = 0.0f;
    if (i < B_ * A_) g_count[i] = 0;
}
// aspect_w permute: g_awT4[((k>>2)*32 + a)*4 + (k&3)] = aw[a][k]
__global__ void transpose_aw_kernel(const float* __restrict__ aw) {
    int i = blockIdx.x * blockDim.x + threadIdx.x;
    if (i < A_ * H_) {
        int a = i >> 9, k = i & 511;
        g_awT4[((k >> 2) * 32 + a) * 4 + (k & 3)] = aw[i];
    }
}
// split (item+pos) into bf16 hi/lo; item into bf16 hi only
__global__ void prep_kernel(const float* __restrict__ item, const float* __restrict__ pos) {
    int i = blockIdx.x * 256 + threadIdx.x;          // float4 index
    if (i >= M_ * H_ / 4) return;
    int col = (i * 4) & 511;
    int s = ((i * 4) >> 9) % S_;
    float4 v = *(const float4*)&item[i * 4];
    float4 p = *(const float4*)&pos[s * H_ + col];
    uint2 h1, h0, l0;
    h1.x = pk_bf16x2(v.x, v.y);
    h1.y = pk_bf16x2(v.z, v.w);
    split_pk(v.x + p.x, v.y + p.y, h0.x, l0.x);
    split_pk(v.z + p.z, v.w + p.w, h0.y, l0.y);
    *(uint2*)&g_A1h[i * 4] = h1;
    *(uint2*)&g_A0h[i * 4] = h0;
    *(uint2*)&g_A0l[i * 4] = l0;
}
// transpose + split the 512x512 weight
__global__ void transpose_w_kernel(const float* __restrict__ W) {
    __shared__ float ts[32][33];
    int bx = blockIdx.x & 15, by = blockIdx.x >> 4;
    int tx = threadIdx.x & 31, ty = threadIdx.x >> 5;
#pragma unroll
    for (int r = 0; r < 4; r++)
        ts[ty + r * 8][tx] = W[(by * 32 + ty + r * 8) * H_ + bx * 32 + tx];
    __syncthreads();
#pragma unroll
    for (int r = 0; r < 4; r++) {
        float val = ts[tx][ty + r * 8];
        int idx = (bx * 32 + ty + r * 8) * H_ + by * 32 + tx;
        __nv_bfloat16 h = __float2bfloat16_rn(val);
        g_wThi[idx] = h;
        g_wTlo[idx] = __float2bfloat16_rn(val - __bfloat162float(h));
    }
}

// ====== bf16 GEMM, 512thr 256x128 tile ======================================
// MODE 0 (attention): 3-term C = Ah@Wh + Ah@Wl + Al@Wh (near-fp32)
//        epilogue leaky(acc+b1)*w2 row-reduce -> atomicAdd g_w.
// MODE 1 (moe): 2-term C = Ah@Wh + Ah@Wl  (single-operand bf16 accuracy)
//        epilogue tanh(acc+lin_b)+item -> g_moe.  AL region unused.
#define AH_OFF 0
#define AL_OFF 32768
#define BH_OFF 65536
#define BL_OFF 81920
#define STG10 98304                      // per stage
#define RED10 (2 * STG10)                // 196608
#define SMEM_G (RED10 + 1024*4 + 128*4 + 128*4)

template <int MODE>
__global__ void __launch_bounds__(512, 1) gemm10(
    const __nv_bfloat16* __restrict__ Ahi, const __nv_bfloat16* __restrict__ Alo,
    const float* __restrict__ Amat,
    const float* __restrict__ p0g, const float* __restrict__ p1g) {
    extern __shared__ char smem[];
    float* red = (float*)(smem + RED10);         // [4][256]
    float* P0  = red + 1024;
    float* P1  = P0 + 128;

    const int tid = threadIdx.x;
    const int lane = tid & 31;
    const int wid = tid >> 5;
    const int g = lane >> 2, q = lane & 3;
    const int warp_m = wid & 3;
    const int warp_n = wid >> 2;
    const int row0 = blockIdx.y * 256;
    const int n0 = blockIdx.x * 128;
    const uint32_t sbase = smem_u32(smem);

    const int lmA = lane & 15;
    const int uhA = lane >> 4;
    const int lmB = (lane & 7) + ((lane >> 4) << 3);
    const int uhB = (lane >> 3) & 1;

    if (tid < 128) {
        P0[tid] = p0g[n0 + tid];
        if (MODE == 0) P1[tid] = p1g[n0 + tid];
    }

    float c[4][4][4];
#pragma unroll
    for (int mf = 0; mf < 4; mf++)
#pragma unroll
        for (int nf = 0; nf < 4; nf++)
#pragma unroll
            for (int i = 0; i < 4; i++) c[mf][nf][i] = 0.0f;

    auto issue = [&](int ch, int st) {
        const int k0 = ch * 64;
        const uint32_t base = sbase + st * STG10;
#pragma unroll
        for (int u = 0; u < 4; u++) {
            int un = tid + u * 512;
            int r = un >> 3, cu = un & 7;
            uint32_t dd = SWZ((uint32_t)(r * 128 + cu * 16));
            CP_ASYNC16(base + AH_OFF + dd, &Ahi[(size_t)(row0 + r) * H_ + k0 + cu * 8]);
            if (MODE == 0)
                CP_ASYNC16(base + AL_OFF + dd, &Alo[(size_t)(row0 + r) * H_ + k0 + cu * 8]);
        }
#pragma unroll
        for (int u = 0; u < 2; u++) {
            int un = tid + u * 512;
            int r = un >> 3, cu = un & 7;
            uint32_t dd = SWZ((uint32_t)(r * 128 + cu * 16));
            CP_ASYNC16(base + BH_OFF + dd, &g_wThi[(size_t)(n0 + r) * H_ + k0 + cu * 8]);
            CP_ASYNC16(base + BL_OFF + dd, &g_wTlo[(size_t)(n0 + r) * H_ + k0 + cu * 8]);
        }
    };

    issue(0, 0); CP_COMMIT();
    issue(1, 1); CP_COMMIT();

    const int mb = warp_m * 64;
    const int nb = warp_n * 32;
#pragma unroll 1
    for (int ch = 0; ch < 8; ch++) {
        CP_WAIT1();
        __syncthreads();
        const uint32_t Sb = sbase + (ch & 1) * STG10;
#pragma unroll
        for (int ks = 0; ks < 4; ks++) {
            uint32_t aoff[4], boff[2];
#pragma unroll
            for (int mf = 0; mf < 4; mf++)
                aoff[mf] = SWZ((uint32_t)((mb + mf * 16 + lmA) * 128 + (2 * ks + uhA) * 16));
#pragma unroll
            for (int nh = 0; nh < 2; nh++)
                boff[nh] = SWZ((uint32_t)((nb + nh * 16 + lmB) * 128 + (2 * ks + uhB) * 16));

            uint32_t af[4][4], bh[2][4], bl[2][4];
#pragma unroll
            for (int mf = 0; mf < 4; mf++) ldm4(af[mf], Sb + AH_OFF + aoff[mf]);
#pragma unroll
            for (int nh = 0; nh < 2; nh++) ldm4(bh[nh], Sb + BH_OFF + boff[nh]);
#pragma unroll
            for (int mf = 0; mf < 4; mf++)
#pragma unroll
                for (int nf = 0; nf < 4; nf++)
                    mma_bf16(c[mf][nf], af[mf], bh[nf >> 1][(nf & 1) * 2],
                             bh[nf >> 1][(nf & 1) * 2 + 1]);
#pragma unroll
            for (int nh = 0; nh < 2; nh++) ldm4(bl[nh], Sb + BL_OFF + boff[nh]);
#pragma unroll
            for (int mf = 0; mf < 4; mf++)
#pragma unroll
                for (int nf = 0; nf < 4; nf++)
                    mma_bf16(c[mf][nf], af[mf], bl[nf >> 1][(nf & 1) * 2],
                             bl[nf >> 1][(nf & 1) * 2 + 1]);
            if (MODE == 0) {
                // 3rd term: reuse af registers for Al fragments
#pragma unroll
                for (int mf = 0; mf < 4; mf++) ldm4(af[mf], Sb + AL_OFF + aoff[mf]);
#pragma unroll
                for (int mf = 0; mf < 4; mf++)
#pragma unroll
                    for (int nf = 0; nf < 4; nf++)
                        mma_bf16(c[mf][nf], af[mf], bh[nf >> 1][(nf & 1) * 2],
                                 bh[nf >> 1][(nf & 1) * 2 + 1]);
            }
        }
        __syncthreads();
        if (ch + 2 < 8) { issue(ch + 2, ch & 1); CP_COMMIT(); }
    }

    if (MODE == 1) {
#pragma unroll
        for (int mf = 0; mf < 4; mf++) {
            int r = row0 + mb + mf * 16 + g;
#pragma unroll
            for (int nf = 0; nf < 4; nf++) {
                int lc = nb + nf * 8 + 2 * q;
                int col = n0 + lc;
                float2 res0 = *(const float2*)&Amat[(size_t)r * H_ + col];
                float2 res1 = *(const float2*)&Amat[(size_t)(r + 8) * H_ + col];
                float2 o0, o1;
                o0.x = tanhf(c[mf][nf][0] + P0[lc]) + res0.x;
                o0.y = tanhf(c[mf][nf][1] + P0[lc + 1]) + res0.y;
                o1.x = tanhf(c[mf][nf][2] + P0[lc]) + res1.x;
                o1.y = tanhf(c[mf][nf][3] + P0[lc + 1]) + res1.y;
                *(float2*)&g_moe[(size_t)r * H_ + col] = o0;
                *(float2*)&g_moe[(size_t)(r + 8) * H_ + col] = o1;
            }
        }
    } else {
        float pr[4][2];
#pragma unroll
        for (int mf = 0; mf < 4; mf++) { pr[mf][0] = 0.0f; pr[mf][1] = 0.0f; }
#pragma unroll
        for (int mf = 0; mf < 4; mf++)
#pragma unroll
            for (int nf = 0; nf < 4; nf++) {
                int lc = nb + nf * 8 + 2 * q;
                float h;
                h = c[mf][nf][0] + P0[lc];     h = (h > 0.f) ? h : 0.01f * h; pr[mf][0] += h * P1[lc];
                h = c[mf][nf][1] + P0[lc + 1]; h = (h > 0.f) ? h : 0.01f * h; pr[mf][0] += h * P1[lc + 1];
                h = c[mf][nf][2] + P0[lc];     h = (h > 0.f) ? h : 0.01f * h; pr[mf][1] += h * P1[lc];
                h = c[mf][nf][3] + P0[lc + 1]; h = (h > 0.f) ? h : 0.01f * h; pr[mf][1] += h * P1[lc + 1];
            }
#pragma unroll
        for (int mf = 0; mf < 4; mf++)
#pragma unroll
            for (int o = 1; o < 4; o <<= 1) {
                pr[mf][0] += __shfl_xor_sync(0xffffffffu, pr[mf][0], o);
                pr[mf][1] += __shfl_xor_sync(0xffffffffu, pr[mf][1], o);
            }
        if (q == 0) {
#pragma unroll
            for (int mf = 0; mf < 4; mf++) {
                red[warp_n * 256 + mb + mf * 16 + g] = pr[mf][0];
                red[warp_n * 256 + mb + mf * 16 + g + 8] = pr[mf][1];
            }
        }
        __syncthreads();
        if (tid < 256) {
            float s = red[tid] + red[256 + tid] + red[512 + tid] + red[768 + tid];
            atomicAdd(&g_w[row0 + tid], s);
        }
    }
}

// ---------------- tma softmax over S per batch ----------------
__global__ void tma_softmax_kernel(const int* __restrict__ seq) {
    int b = blockIdx.x;
    int t = threadIdx.x;
    __shared__ float sd[256];
    float v = -3.4e38f;
    if (t < S_) v = (seq[b * S_ + t] == 0) ? NEGV : g_w[b * S_ + t];
    sd[t] = v;
    __syncthreads();
    for (int o = 128; o; o >>= 1) { if (t < o) sd[t] = fmaxf(sd[t], sd[t + o]); __syncthreads(); }
    float m = sd[0];
    __syncthreads();
    float e = (t < S_) ? expf(v - m) : 0.0f;
    sd[t] = e;
    __syncthreads();
    for (int o = 128; o; o >>= 1) { if (t < o) sd[t] += sd[t + o]; __syncthreads(); }
    float s = sd[0];
    if (t < S_) g_w[b * S_ + t] = e / s;
}

// ---------------- LayerNorm over H, in place on g_moe ----------------
__global__ void ln_kernel(const float* __restrict__ gam, const float* __restrict__ bet) {
    int row = blockIdx.x * 8 + (threadIdx.x >> 5);
    int lane = threadIdx.x & 31;
    float* p = &g_moe[(size_t)row * H_];
    float4 x[4];
    float sum = 0.0f;
#pragma unroll
    for (int q = 0; q < 4; q++) {
        x[q] = *(float4*)&p[lane * 4 + q * 128];
        sum += x[q].x + x[q].y + x[q].z + x[q].w;
    }
    for (int o = 16; o; o >>= 1) sum += __shfl_xor_sync(0xffffffffu, sum, o);
    float mu = sum * (1.0f / H_);
    float sq = 0.0f;
#pragma unroll
    for (int q = 0; q < 4; q++) {
        float a = x[q].x - mu, bb = x[q].y - mu, c = x[q].z - mu, d = x[q].w - mu;
        sq += a * a + bb * bb + c * c + d * d;
    }
    for (int o = 16; o; o >>= 1) sq += __shfl_xor_sync(0xffffffffu, sq, o);
    float rs = rsqrtf(sq * (1.0f / H_) + 1e-12f);
#pragma unroll
    for (int q = 0; q < 4; q++) {
        int col = lane * 4 + q * 128;
        float4 o4;
        o4.x = (x[q].x - mu) * rs * gam[col + 0] + bet[col + 0];
        o4.y = (x[q].y - mu) * rs * gam[col + 1] + bet[col + 1];
        o4.z = (x[q].z - mu) * rs * gam[col + 2] + bet[col + 2];
        o4.w = (x[q].w - mu) * rs * gam[col + 3] + bet[col + 3];
        *(float4*)&p[col] = o4;
    }
}

// ---------------- gates (exact fp32, float4 order-preserving) --------------
// warp = row. 128 iters: broadcast LDG.128 item + coalesced LDG.128 awT4 +
// 4 sequential fmaf (ascending k) -> bit-identical logits to the scalar loop.
__launch_bounds__(256)
__global__ void gates_kernel(const float* __restrict__ item, const int* __restrict__ seq,
                             float* __restrict__ out_gsm) {
    int tid = threadIdx.x, w = tid >> 5, lane = tid & 31;
    int row = blockIdx.x * 8 + w;
    const float4* xr = (const float4*)&item[(size_t)row * H_];
    const float4* ar = (const float4*)g_awT4;
    float acc = 0.0f;
#pragma unroll 8
    for (int k4 = 0; k4 < 128; k4++) {
        float4 xv = xr[k4];
        float4 av = ar[k4 * 32 + lane];
        acc = fmaf(xv.x, av.x, acc);
        acc = fmaf(xv.y, av.y, acc);
        acc = fmaf(xv.z, av.z, acc);
        acc = fmaf(xv.w, av.w, acc);
    }
    float mv = acc;
    int mi = lane;
    for (int o = 16; o; o >>= 1) {
        float ov = __shfl_xor_sync(0xffffffffu, mv, o);
        int oi = __shfl_xor_sync(0xffffffffu, mi, o);
        if (ov > mv || (ov == mv && oi < mi)) { mv = ov; mi = oi; }
    }
    float e = expf(acc - mv);
    float s = e;
    for (int o = 16; o; o >>= 1) s += __shfl_xor_sync(0xffffffffu, s, o);
    out_gsm[(size_t)row * A_ + lane] = e / s;
    g_bij[(size_t)row * A_ + lane] = acc;
    if (lane == 0 && seq[row] != 0) atomicAdd(&g_count[(row / S_) * A_ + mi], 1);
}

__global__ void mask_kernel(float* __restrict__ out_mask) {
    int i = blockIdx.x * blockDim.x + threadIdx.x;
    if (i < B_ * A_) out_mask[i] = (g_count[i] == 0) ? 1.0f : 0.0f;
}

// ---------------- routing: cijt = softmax(masked bij) * tma (exact) ------
__global__ void cijt_kernel(const int* __restrict__ seq) {
    int tid = threadIdx.x, w = tid >> 5, lane = tid & 31;
    int row = blockIdx.x * 8 + w;
    int b = row / S_;
    float v = (g_count[b * A_ + lane] == 0) ? NEGV : g_bij[row * A_ + lane];
    float mv = v;
    for (int o = 16; o; o >>= 1) mv = fmaxf(mv, __shfl_xor_sync(0xffffffffu, mv, o));
    float e = expf(v - mv);
    float s = e;
    for (int o = 16; o; o >>= 1) s += __shfl_xor_sync(0xffffffffu, s, o);
    float c = e / s;
    if (seq[row] == 0) c = 0.0f;
    g_cijt[row * A_ + lane] = c * g_w[row];
}

// ==== cap_tc: tf32 mma cap GEMM + fused squash. One CTA (256thr) per batch ==
#define CW_ST 40
#define MO_ST 520
#define CAP_ST 516
#define CAP_SMEMF (8000 + 12480 + 32)
__global__ void __launch_bounds__(256, 1) cap_tc(float* __restrict__ cap) {
    extern __shared__ float sm[];
    float* cw = sm;                        // [200][40]
    float* moed = sm + 8000;               // [3][8][520]
    float* capsm = sm;                     // overlay [32][516]
    float* scale = sm + 8000 + 12480;      // [32]
    const int b = blockIdx.x;
    const int tid = threadIdx.x, lane = tid & 31, wid = tid >> 5;
    const int g = lane >> 2, q = lane & 3;
    const int h0 = wid * 64;
    const uint32_t sbase = smem_u32(sm);

    auto issue = [&](int kc, int st) {
        const float* src = &g_moe[((size_t)b * S_ + kc * 8) * H_];
#pragma unroll
        for (int u = 0; u < 4; u++) {
            int un = tid + u * 256;
            int r = un >> 7, c4 = un & 127;
            CP_ASYNC16(sbase + (8000 + st * 8 * MO_ST + r * MO_ST + c4 * 4) * 4,
                       src + r * H_ + c4 * 4);
        }
    };
    issue(0, 0); CP_COMMIT();
    issue(1, 1); CP_COMMIT();

    {
        const float4* src = (const float4*)&g_cijt[(size_t)b * S_ * A_];
        for (int i = tid; i < S_ * 8; i += 256) {
            int s = i >> 3, c4 = i & 7;
            float4 v = src[i];
            cw[s * CW_ST + c4 * 4 + 0] = __uint_as_float(f2tf32(v.x));
            cw[s * CW_ST + c4 * 4 + 1] = __uint_as_float(f2tf32(v.y));
            cw[s * CW_ST + c4 * 4 + 2] = __uint_as_float(f2tf32(v.z));
            cw[s * CW_ST + c4 * 4 + 3] = __uint_as_float(f2tf32(v.w));
        }
    }

    float acc[2][8][4];
#pragma unroll
    for (int mi = 0; mi < 2; mi++)
#pragma unroll
        for (int ni = 0; ni < 8; ni++)
#pragma unroll
            for (int i = 0; i < 4; i++) acc[mi][ni][i] = 0.0f;

#pragma unroll 1
    for (int kc = 0; kc < 25; kc++) {
        if (kc + 2 < 25) issue(kc + 2, (kc + 2) % 3);
        CP_COMMIT();
        CP_WAIT2();
        __syncthreads();
        const float* mb = moed + (kc % 3) * 8 * MO_ST;
        uint32_t a0[2][4];
#pragma unroll
        for (int mi = 0; mi < 2; mi++) {
            a0[mi][0] = __float_as_uint(cw[(kc * 8 + q) * CW_ST + mi * 16 + g]);
            a0[mi][1] = __float_as_uint(cw[(kc * 8 + q) * CW_ST + mi * 16 + g + 8]);
            a0[mi][2] = __float_as_uint(cw[(kc * 8 + q + 4) * CW_ST + mi * 16 + g]);
            a0[mi][3] = __float_as_uint(cw[(kc * 8 + q + 4) * CW_ST + mi * 16 + g + 8]);
        }
#pragma unroll
        for (int ni = 0; ni < 8; ni++) {
            uint32_t b0 = f2tf32(mb[q * MO_ST + h0 + ni * 8 + g]);
            uint32_t b1 = f2tf32(mb[(q + 4) * MO_ST + h0 + ni * 8 + g]);
            mma_tf32(acc[0][ni], a0[0][0], a0[0][1], a0[0][2], a0[0][3], b0, b1);
            mma_tf32(acc[1][ni], a0[1][0], a0[1][1], a0[1][2], a0[1][3], b0, b1);
        }
        __syncthreads();
    }

    __syncthreads();
#pragma unroll
    for (int mi = 0; mi < 2; mi++)
#pragma unroll
        for (int ni = 0; ni < 8; ni++) {
            int cc = h0 + ni * 8 + 2 * q;
            capsm[(mi * 16 + g) * CAP_ST + cc]     = acc[mi][ni][0];
            capsm[(mi * 16 + g) * CAP_ST + cc + 1] = acc[mi][ni][1];
            capsm[(mi * 16 + g + 8) * CAP_ST + cc]     = acc[mi][ni][2];
            capsm[(mi * 16 + g + 8) * CAP_ST + cc + 1] = acc[mi][ni][3];
        }
    __syncthreads();
    {
        int a = tid >> 3, sub = tid & 7;
        float sq = 0.0f;
        const float* pr = &capsm[a * CAP_ST + sub * 64];
#pragma unroll 8
        for (int j = 0; j < 64; j++) sq += pr[j] * pr[j];
        sq += __shfl_xor_sync(0xffffffffu, sq, 1);
        sq += __shfl_xor_sync(0xffffffffu, sq, 2);
        sq += __shfl_xor_sync(0xffffffffu, sq, 4);
        if (sub == 0) scale[a] = sq / ((1.0f + sq) * sqrtf(sq + 1e-9f));
    }
    __syncthreads();
#pragma unroll 1
    for (int j = 0; j < 64; j++) {
        int i = tid + j * 256;
        int a = i >> 9, h = i & 511;
        cap[((size_t)b * A_ + a) * H_ + h] = capsm[a * CAP_ST + h] * scale[a];
    }
}

// ==== bij_tc: tf32 mma  bij[s][a] += moe[s,:] . cap[a,:]. One CTA per batch =
#define BMO_ST 40
#define BIJ_SMEMF (16512 + 20480)
__global__ void __launch_bounds__(256, 1) bij_tc(const float* __restrict__ cap) {
    extern __shared__ float sm[];
    float* capsm = sm;                       // [32][516]
    float* moesm = sm + 16512;               // [8][2][32][40]
    const int b = blockIdx.x;
    const int tid = threadIdx.x, lane = tid & 31, w = tid >> 5;
    const int g = lane >> 2, q = lane & 3;
    const uint32_t sbase = smem_u32(sm);

    {
        const float4* src = (const float4*)&cap[(size_t)b * A_ * H_];
        for (int j = 0; j < 16; j++) {
            int i = tid + j * 256;
            int a = i >> 7, c4 = i & 127;
            *(float4*)&capsm[a * CAP_ST + c4 * 4] = src[i];
        }
    }
    __syncthreads();

    float* msw = moesm + w * 2 * 32 * BMO_ST;
    const uint32_t mswb = sbase + (16512 + w * 2 * 32 * BMO_ST) * 4;
    const int row_base = w * 32;

    auto issue = [&](int kc, int st) {
#pragma unroll
        for (int j = 0; j < 8; j++) {
            int idx = lane + j * 32;
            int r = idx >> 3, c4 = idx & 7;
            int srow = row_base + r; if (srow > S_ - 1) srow = S_ - 1;
            CP_ASYNC16(mswb + (st * 32 * BMO_ST + r * BMO_ST + c4 * 4) * 4,
                       &g_moe[((size_t)b * S_ + srow) * H_ + kc * 32 + c4 * 4]);
        }
    };

    float acc[2][4][4];
#pragma unroll
    for (int mi = 0; mi < 2; mi++)
#pragma unroll
        for (int ni = 0; ni < 4; ni++)
#pragma unroll
            for (int i = 0; i < 4; i++) acc[mi][ni][i] = 0.0f;

    if (row_base < S_) {
        issue(0, 0); CP_COMMIT();
        issue(1, 1); CP_COMMIT();
#pragma unroll 1
        for (int kc = 0; kc < 16; kc++) {
            CP_WAIT1();
            __syncwarp();
            const float* ms = msw + (kc & 1) * 32 * BMO_ST;
#pragma unroll
            for (int ks = 0; ks < 4; ks++) {
                int k = ks * 8;
                uint32_t a0[2][4];
#pragma unroll
                for (int mi = 0; mi < 2; mi++) {
                    a0[mi][0] = f2tf32(ms[(mi * 16 + g) * BMO_ST + k + q]);
                    a0[mi][1] = f2tf32(ms[(mi * 16 + g + 8) * BMO_ST + k + q]);
                    a0[mi][2] = f2tf32(ms[(mi * 16 + g) * BMO_ST + k + q + 4]);
                    a0[mi][3] = f2tf32(ms[(mi * 16 + g + 8) * BMO_ST + k + q + 4]);
                }
                int K0 = kc * 32 + k;
#pragma unroll
                for (int ni = 0; ni < 4; ni++) {
                    uint32_t b0 = f2tf32(capsm[(ni * 8 + g) * CAP_ST + K0 + q]);
                    uint32_t b1 = f2tf32(capsm[(ni * 8 + g) * CAP_ST + K0 + q + 4]);
                    mma_tf32(acc[0][ni], a0[0][0], a0[0][1], a0[0][2], a0[0][3], b0, b1);
                    mma_tf32(acc[1][ni], a0[1][0], a0[1][1], a0[1][2], a0[1][3], b0, b1);
                }
            }
            __syncwarp();
            if (kc + 2 < 16) { issue(kc + 2, kc & 1); CP_COMMIT(); }
        }
#pragma unroll
        for (int mi = 0; mi < 2; mi++) {
            int r = row_base + mi * 16 + g;
#pragma unroll
            for (int ni = 0; ni < 4; ni++) {
                int cc = ni * 8 + 2 * q;
                if (r < S_) {
                    float2* p = (float2*)&g_bij[((size_t)b * S_ + r) * A_ + cc];
                    float2 v = *p; v.x += acc[mi][ni][0]; v.y += acc[mi][ni][1]; *p = v;
                }
                if (r + 8 < S_) {
                    float2* p = (float2*)&g_bij[((size_t)b * S_ + r + 8) * A_ + cc];
                    float2 v = *p; v.x += acc[mi][ni][2]; v.y += acc[mi][ni][3]; *p = v;
                }
            }
        }
    }
}

// ---------------- host ----------------
extern "C" void kernel_launch(void* const* d_in, const int* in_sizes, int n_in,
                              void* d_out, int out_size) {
    const float* item = (const float*)d_in[0];
    const int*   seq  = (const int*)d_in[1];
    const float* pos  = (const float*)d_in[2];
    const float* w1   = (const float*)d_in[3];
    const float* b1   = (const float*)d_in[4];
    const float* w2   = (const float*)d_in[5];
    // d_in[6] = attn_b2: softmax-invariant constant shift, a no-op
    const float* lw   = (const float*)d_in[7];
    const float* lb   = (const float*)d_in[8];
    const float* aw   = (const float*)d_in[9];
    const float* lng  = (const float*)d_in[10];
    const float* lnb  = (const float*)d_in[11];

    const size_t CAPN = (size_t)B_ * A_ * H_;
    const size_t GSN  = (size_t)M_ * A_;
    const size_t MKN  = (size_t)B_ * A_;

    float* out_cap = (float*)d_out;
    float* out_gsm;
    float* out_mask;
    if ((size_t)out_size >= CAPN + GSN + MKN) {
        out_gsm  = out_cap + CAPN;
        out_mask = out_cap + CAPN + GSN;
    } else {
        void* p;
        cudaGetSymbolAddress(&p, g_dummy_gates); out_gsm = (float*)p;
        cudaGetSymbolAddress(&p, g_dummy_mask);  out_mask = (float*)p;
    }

    cudaFuncSetAttribute(gemm10<0>, cudaFuncAttributeMaxDynamicSharedMemorySize, SMEM_G);
    cudaFuncSetAttribute(gemm10<1>, cudaFuncAttributeMaxDynamicSharedMemorySize, SMEM_G);
    cudaFuncSetAttribute(cap_tc, cudaFuncAttributeMaxDynamicSharedMemorySize, CAP_SMEMF * 4);
    cudaFuncSetAttribute(bij_tc, cudaFuncAttributeMaxDynamicSharedMemorySize, BIJ_SMEMF * 4);

    __nv_bfloat16 *a0h, *a0l, *a1h;
    { void* p;
      cudaGetSymbolAddress(&p, g_A0h); a0h = (__nv_bfloat16*)p;
      cudaGetSymbolAddress(&p, g_A0l); a0l = (__nv_bfloat16*)p;
      cudaGetSymbolAddress(&p, g_A1h); a1h = (__nv_bfloat16*)p; }

    // launch order: gemm10<0> is 4th launch -> ncu capture slot
    prep_kernel<<<(M_ * H_ / 4 + 255) / 256, 256>>>(item, pos);
    zero_kernel<<<(M_ + 255) / 256, 256>>>();
    transpose_w_kernel<<<256, 256>>>(w1);
    gemm10<0><<<dim3(4, 400), 512, SMEM_G>>>(a0h, a0l, item, b1, w2);
    tma_softmax_kernel<<<B_, 256>>>(seq);

    transpose_w_kernel<<<256, 256>>>(lw);
    gemm10<1><<<dim3(4, 400), 512, SMEM_G>>>(a1h, a1h, item, lb, nullptr);
    ln_kernel<<<M_ / 8, 256>>>(lng, lnb);

    transpose_aw_kernel<<<(A_ * H_ + 255) / 256, 256>>>(aw);
    gates_kernel<<<M_ / 8, 256>>>(item, seq, out_gsm);
    mask_kernel<<<(B_ * A_ + 255) / 256, 256>>>(out_mask);

    for (int t = 0; t < 3; t++) {
        cijt_kernel<<<M_ / 8, 256>>>(seq);
        cap_tc<<<B_, 256, CAP_SMEMF * 4>>>(out_cap);
        if (t < 2) bij_tc<<<B_, 256, BIJ_SMEMF * 4>>>(out_cap);
    }
}

// round 17
// speedup vs baseline: 1.0210x; 1.0210x over previous
#include <cuda_runtime.h>
#include <cuda_bf16.h>
#include <cstdint>
#include <math.h>

#define B_ 512
#define S_ 200
#define H_ 512
#define A_ 32
#define M_ (B_*S_)          // 102400 rows
#define NEGV (-1e9f)

// ---------------- device scratch (no allocations allowed) ----------------
__device__ float g_moe[(M_ + 64) * H_];       // ~210MB
__device__ __nv_bfloat16 g_A0h[M_ * H_];      // bf16 hi of (item+pos)
__device__ __nv_bfloat16 g_A0l[M_ * H_];      // bf16 lo residual
__device__ __nv_bfloat16 g_A1h[M_ * H_];      // bf16 hi of item (2-term: no lo)
__device__ float g_w[M_];
__device__ float g_bij[M_ * A_];
__device__ float g_cijt[M_ * A_];
__device__ float g_awT[H_ * A_];              // aspect_w transposed [k][a]
__device__ __nv_bfloat16 g_wThi[H_ * H_];     // W^T hi [n][k]
__device__ __nv_bfloat16 g_wTlo[H_ * H_];     // W^T lo
__device__ int   g_count[B_ * A_];
__device__ float g_dummy_gates[M_ * A_];
__device__ float g_dummy_mask[B_ * A_];

// ---------------- PTX helpers (family-portable) ----------------
__device__ __forceinline__ uint32_t smem_u32(const void* p) {
    uint32_t a;
    asm("{ .reg .u64 t; cvta.to.shared.u64 t, %1; cvt.u32.u64 %0, t; }" : "=r"(a) : "l"(p));
    return a;
}
__device__ __forceinline__ void ldm4(uint32_t r[4], uint32_t addr) {
    asm volatile("ldmatrix.sync.aligned.m8n8.x4.shared.b16 {%0,%1,%2,%3}, [%4];"
                 : "=r"(r[0]), "=r"(r[1]), "=r"(r[2]), "=r"(r[3]) : "r"(addr));
}
__device__ __forceinline__ void mma_bf16(float c[4], const uint32_t a[4],
                                         uint32_t b0, uint32_t b1) {
    asm volatile(
        "mma.sync.aligned.m16n8k16.row.col.f32.bf16.bf16.f32 "
        "{%0,%1,%2,%3},{%4,%5,%6,%7},{%8,%9},{%0,%1,%2,%3};"
        : "+f"(c[0]), "+f"(c[1]), "+f"(c[2]), "+f"(c[3])
        : "r"(a[0]), "r"(a[1]), "r"(a[2]), "r"(a[3]), "r"(b0), "r"(b1));
}
__device__ __forceinline__ void mma_tf32(float c[4],
                                         uint32_t a0, uint32_t a1, uint32_t a2, uint32_t a3,
                                         uint32_t b0, uint32_t b1) {
    asm volatile(
        "mma.sync.aligned.m16n8k8.row.col.f32.tf32.tf32.f32 "
        "{%0,%1,%2,%3},{%4,%5,%6,%7},{%8,%9},{%0,%1,%2,%3};"
        : "+f"(c[0]), "+f"(c[1]), "+f"(c[2]), "+f"(c[3])
        : "r"(a0), "r"(a1), "r"(a2), "r"(a3), "r"(b0), "r"(b1));
}
__device__ __forceinline__ uint32_t f2tf32(float x) {
    uint32_t y;
    asm("cvt.rna.tf32.f32 %0, %1;" : "=r"(y) : "f"(x));
    return y;
}
__device__ __forceinline__ void split_pk(float x, float y, uint32_t& hi, uint32_t& lo) {
    __nv_bfloat162 h = __float22bfloat162_rn(make_float2(x, y));
    float hx = __bfloat162float(h.x), hy = __bfloat162float(h.y);
    __nv_bfloat162 l = __float22bfloat162_rn(make_float2(x - hx, y - hy));
    hi = *(uint32_t*)&h;
    lo = *(uint32_t*)&l;
}
__device__ __forceinline__ uint32_t pk_bf16x2(float x, float y) {
    __nv_bfloat162 t = __float22bfloat162_rn(make_float2(x, y));
    return *(uint32_t*)&t;
}
#define CP_ASYNC16(dst, src) \
    asm volatile("cp.async.cg.shared.global [%0], [%1], 16;" :: "r"(dst), "l"(src))
#define CP_COMMIT() asm volatile("cp.async.commit_group;" ::: "memory")
#define CP_WAIT2()  asm volatile("cp.async.wait_group 2;" ::: "memory")
#define CP_WAIT1()  asm volatile("cp.async.wait_group 1;" ::: "memory")
#define SWZ(off) ((off) ^ (((off) >> 3) & 0x70))

// ---------------- init ----------------
__global__ void zero_kernel() {
    int i = blockIdx.x * blockDim.x + threadIdx.x;
    if (i < M_) g_w[i] = 0.0f;
    if (i < B_ * A_) g_count[i] = 0;
}
__global__ void transpose_aw_kernel(const float* __restrict__ aw) {
    int i = blockIdx.x * blockDim.x + threadIdx.x;
    if (i < A_ * H_) {
        int a = i >> 9, k = i & 511;
        g_awT[k * A_ + a] = aw[i];
    }
}
// split (item+pos) into bf16 hi/lo; item into bf16 hi only
__global__ void prep_kernel(const float* __restrict__ item, const float* __restrict__ pos) {
    int i = blockIdx.x * 256 + threadIdx.x;          // float4 index
    if (i >= M_ * H_ / 4) return;
    int col = (i * 4) & 511;
    int s = ((i * 4) >> 9) % S_;
    float4 v = *(const float4*)&item[i * 4];
    float4 p = *(const float4*)&pos[s * H_ + col];
    uint2 h1, h0, l0;
    h1.x = pk_bf16x2(v.x, v.y);
    h1.y = pk_bf16x2(v.z, v.w);
    split_pk(v.x + p.x, v.y + p.y, h0.x, l0.x);
    split_pk(v.z + p.z, v.w + p.w, h0.y, l0.y);
    *(uint2*)&g_A1h[i * 4] = h1;
    *(uint2*)&g_A0h[i * 4] = h0;
    *(uint2*)&g_A0l[i * 4] = l0;
}
// transpose + split the 512x512 weight
__global__ void transpose_w_kernel(const float* __restrict__ W) {
    __shared__ float ts[32][33];
    int bx = blockIdx.x & 15, by = blockIdx.x >> 4;
    int tx = threadIdx.x & 31, ty = threadIdx.x >> 5;
#pragma unroll
    for (int r = 0; r < 4; r++)
        ts[ty + r * 8][tx] = W[(by * 32 + ty + r * 8) * H_ + bx * 32 + tx];
    __syncthreads();
#pragma unroll
    for (int r = 0; r < 4; r++) {
        float val = ts[tx][ty + r * 8];
        int idx = (bx * 32 + ty + r * 8) * H_ + by * 32 + tx;
        __nv_bfloat16 h = __float2bfloat16_rn(val);
        g_wThi[idx] = h;
        g_wTlo[idx] = __float2bfloat16_rn(val - __bfloat162float(h));
    }
}

// ====== bf16 GEMM, 512thr 256x128 tile ======================================
// MODE 0 (attention): 3-term C = Ah@Wh + Ah@Wl + Al@Wh (near-fp32)
//        epilogue leaky(acc+b1)*w2 row-reduce -> atomicAdd g_w.
// MODE 1 (moe): 2-term C = Ah@Wh + Ah@Wl  (single-operand bf16 accuracy)
//        epilogue tanh(acc+lin_b)+item -> g_moe.  AL region unused.
#define AH_OFF 0
#define AL_OFF 32768
#define BH_OFF 65536
#define BL_OFF 81920
#define STG10 98304                      // per stage
#define RED10 (2 * STG10)                // 196608
#define SMEM_G (RED10 + 1024*4 + 128*4 + 128*4)

template <int MODE>
__global__ void __launch_bounds__(512, 1) gemm10(
    const __nv_bfloat16* __restrict__ Ahi, const __nv_bfloat16* __restrict__ Alo,
    const float* __restrict__ Amat,
    const float* __restrict__ p0g, const float* __restrict__ p1g) {
    extern __shared__ char smem[];
    float* red = (float*)(smem + RED10);         // [4][256]
    float* P0  = red + 1024;
    float* P1  = P0 + 128;

    const int tid = threadIdx.x;
    const int lane = tid & 31;
    const int wid = tid >> 5;
    const int g = lane >> 2, q = lane & 3;
    const int warp_m = wid & 3;
    const int warp_n = wid >> 2;
    const int row0 = blockIdx.y * 256;
    const int n0 = blockIdx.x * 128;
    const uint32_t sbase = smem_u32(smem);

    const int lmA = lane & 15;
    const int uhA = lane >> 4;
    const int lmB = (lane & 7) + ((lane >> 4) << 3);
    const int uhB = (lane >> 3) & 1;

    if (tid < 128) {
        P0[tid] = p0g[n0 + tid];
        if (MODE == 0) P1[tid] = p1g[n0 + tid];
    }

    float c[4][4][4];
#pragma unroll
    for (int mf = 0; mf < 4; mf++)
#pragma unroll
        for (int nf = 0; nf < 4; nf++)
#pragma unroll
            for (int i = 0; i < 4; i++) c[mf][nf][i] = 0.0f;

    auto issue = [&](int ch, int st) {
        const int k0 = ch * 64;
        const uint32_t base = sbase + st * STG10;
#pragma unroll
        for (int u = 0; u < 4; u++) {
            int un = tid + u * 512;
            int r = un >> 3, cu = un & 7;
            uint32_t dd = SWZ((uint32_t)(r * 128 + cu * 16));
            CP_ASYNC16(base + AH_OFF + dd, &Ahi[(size_t)(row0 + r) * H_ + k0 + cu * 8]);
            if (MODE == 0)
                CP_ASYNC16(base + AL_OFF + dd, &Alo[(size_t)(row0 + r) * H_ + k0 + cu * 8]);
        }
#pragma unroll
        for (int u = 0; u < 2; u++) {
            int un = tid + u * 512;
            int r = un >> 3, cu = un & 7;
            uint32_t dd = SWZ((uint32_t)(r * 128 + cu * 16));
            CP_ASYNC16(base + BH_OFF + dd, &g_wThi[(size_t)(n0 + r) * H_ + k0 + cu * 8]);
            CP_ASYNC16(base + BL_OFF + dd, &g_wTlo[(size_t)(n0 + r) * H_ + k0 + cu * 8]);
        }
    };

    issue(0, 0); CP_COMMIT();
    issue(1, 1); CP_COMMIT();

    const int mb = warp_m * 64;
    const int nb = warp_n * 32;
#pragma unroll 1
    for (int ch = 0; ch < 8; ch++) {
        CP_WAIT1();
        __syncthreads();
        const uint32_t Sb = sbase + (ch & 1) * STG10;
#pragma unroll
        for (int ks = 0; ks < 4; ks++) {
            uint32_t aoff[4], boff[2];
#pragma unroll
            for (int mf = 0; mf < 4; mf++)
                aoff[mf] = SWZ((uint32_t)((mb + mf * 16 + lmA) * 128 + (2 * ks + uhA) * 16));
#pragma unroll
            for (int nh = 0; nh < 2; nh++)
                boff[nh] = SWZ((uint32_t)((nb + nh * 16 + lmB) * 128 + (2 * ks + uhB) * 16));

            uint32_t af[4][4], bh[2][4], bl[2][4];
#pragma unroll
            for (int mf = 0; mf < 4; mf++) ldm4(af[mf], Sb + AH_OFF + aoff[mf]);
#pragma unroll
            for (int nh = 0; nh < 2; nh++) ldm4(bh[nh], Sb + BH_OFF + boff[nh]);
#pragma unroll
            for (int mf = 0; mf < 4; mf++)
#pragma unroll
                for (int nf = 0; nf < 4; nf++)
                    mma_bf16(c[mf][nf], af[mf], bh[nf >> 1][(nf & 1) * 2],
                             bh[nf >> 1][(nf & 1) * 2 + 1]);
#pragma unroll
            for (int nh = 0; nh < 2; nh++) ldm4(bl[nh], Sb + BL_OFF + boff[nh]);
#pragma unroll
            for (int mf = 0; mf < 4; mf++)
#pragma unroll
                for (int nf = 0; nf < 4; nf++)
                    mma_bf16(c[mf][nf], af[mf], bl[nf >> 1][(nf & 1) * 2],
                             bl[nf >> 1][(nf & 1) * 2 + 1]);
            if (MODE == 0) {
                // 3rd term: reuse af registers for Al fragments
#pragma unroll
                for (int mf = 0; mf < 4; mf++) ldm4(af[mf], Sb + AL_OFF + aoff[mf]);
#pragma unroll
                for (int mf = 0; mf < 4; mf++)
#pragma unroll
                    for (int nf = 0; nf < 4; nf++)
                        mma_bf16(c[mf][nf], af[mf], bh[nf >> 1][(nf & 1) * 2],
                                 bh[nf >> 1][(nf & 1) * 2 + 1]);
            }
        }
        __syncthreads();
        if (ch + 2 < 8) { issue(ch + 2, ch & 1); CP_COMMIT(); }
    }

    if (MODE == 1) {
#pragma unroll
        for (int mf = 0; mf < 4; mf++) {
            int r = row0 + mb + mf * 16 + g;
#pragma unroll
            for (int nf = 0; nf < 4; nf++) {
                int lc = nb + nf * 8 + 2 * q;
                int col = n0 + lc;
                float2 res0 = *(const float2*)&Amat[(size_t)r * H_ + col];
                float2 res1 = *(const float2*)&Amat[(size_t)(r + 8) * H_ + col];
                float2 o0, o1;
                o0.x = tanhf(c[mf][nf][0] + P0[lc]) + res0.x;
                o0.y = tanhf(c[mf][nf][1] + P0[lc + 1]) + res0.y;
                o1.x = tanhf(c[mf][nf][2] + P0[lc]) + res1.x;
                o1.y = tanhf(c[mf][nf][3] + P0[lc + 1]) + res1.y;
                *(float2*)&g_moe[(size_t)r * H_ + col] = o0;
                *(float2*)&g_moe[(size_t)(r + 8) * H_ + col] = o1;
            }
        }
    } else {
        float pr[4][2];
#pragma unroll
        for (int mf = 0; mf < 4; mf++) { pr[mf][0] = 0.0f; pr[mf][1] = 0.0f; }
#pragma unroll
        for (int mf = 0; mf < 4; mf++)
#pragma unroll
            for (int nf = 0; nf < 4; nf++) {
                int lc = nb + nf * 8 + 2 * q;
                float h;
                h = c[mf][nf][0] + P0[lc];     h = (h > 0.f) ? h : 0.01f * h; pr[mf][0] += h * P1[lc];
                h = c[mf][nf][1] + P0[lc + 1]; h = (h > 0.f) ? h : 0.01f * h; pr[mf][0] += h * P1[lc + 1];
                h = c[mf][nf][2] + P0[lc];     h = (h > 0.f) ? h : 0.01f * h; pr[mf][1] += h * P1[lc];
                h = c[mf][nf][3] + P0[lc + 1]; h = (h > 0.f) ? h : 0.01f * h; pr[mf][1] += h * P1[lc + 1];
            }
#pragma unroll
        for (int mf = 0; mf < 4; mf++)
#pragma unroll
            for (int o = 1; o < 4; o <<= 1) {
                pr[mf][0] += __shfl_xor_sync(0xffffffffu, pr[mf][0], o);
                pr[mf][1] += __shfl_xor_sync(0xffffffffu, pr[mf][1], o);
            }
        if (q == 0) {
#pragma unroll
            for (int mf = 0; mf < 4; mf++) {
                red[warp_n * 256 + mb + mf * 16 + g] = pr[mf][0];
                red[warp_n * 256 + mb + mf * 16 + g + 8] = pr[mf][1];
            }
        }
        __syncthreads();
        if (tid < 256) {
            float s = red[tid] + red[256 + tid] + red[512 + tid] + red[768 + tid];
            atomicAdd(&g_w[row0 + tid], s);
        }
    }
}

// ---------------- tma softmax over S per batch ----------------
__global__ void tma_softmax_kernel(const int* __restrict__ seq) {
    int b = blockIdx.x;
    int t = threadIdx.x;
    __shared__ float sd[256];
    float v = -3.4e38f;
    if (t < S_) v = (seq[b * S_ + t] == 0) ? NEGV : g_w[b * S_ + t];
    sd[t] = v;
    __syncthreads();
    for (int o = 128; o; o >>= 1) { if (t < o) sd[t] = fmaxf(sd[t], sd[t + o]); __syncthreads(); }
    float m = sd[0];
    __syncthreads();
    float e = (t < S_) ? expf(v - m) : 0.0f;
    sd[t] = e;
    __syncthreads();
    for (int o = 128; o; o >>= 1) { if (t < o) sd[t] += sd[t + o]; __syncthreads(); }
    float s = sd[0];
    if (t < S_) g_w[b * S_ + t] = e / s;
}

// ---------------- LayerNorm over H, in place on g_moe ----------------
__global__ void ln_kernel(const float* __restrict__ gam, const float* __restrict__ bet) {
    int row = blockIdx.x * 8 + (threadIdx.x >> 5);
    int lane = threadIdx.x & 31;
    float* p = &g_moe[(size_t)row * H_];
    float4 x[4];
    float sum = 0.0f;
#pragma unroll
    for (int q = 0; q < 4; q++) {
        x[q] = *(float4*)&p[lane * 4 + q * 128];
        sum += x[q].x + x[q].y + x[q].z + x[q].w;
    }
    for (int o = 16; o; o >>= 1) sum += __shfl_xor_sync(0xffffffffu, sum, o);
    float mu = sum * (1.0f / H_);
    float sq = 0.0f;
#pragma unroll
    for (int q = 0; q < 4; q++) {
        float a = x[q].x - mu, bb = x[q].y - mu, c = x[q].z - mu, d = x[q].w - mu;
        sq += a * a + bb * bb + c * c + d * d;
    }
    for (int o = 16; o; o >>= 1) sq += __shfl_xor_sync(0xffffffffu, sq, o);
    float rs = rsqrtf(sq * (1.0f / H_) + 1e-12f);
#pragma unroll
    for (int q = 0; q < 4; q++) {
        int col = lane * 4 + q * 128;
        float4 o4;
        o4.x = (x[q].x - mu) * rs * gam[col + 0] + bet[col + 0];
        o4.y = (x[q].y - mu) * rs * gam[col + 1] + bet[col + 1];
        o4.z = (x[q].z - mu) * rs * gam[col + 2] + bet[col + 2];
        o4.w = (x[q].w - mu) * rs * gam[col + 3] + bet[col + 3];
        *(float4*)&p[col] = o4;
    }
}

// ---------------- gates (exact fp32, R15-proven): GEMV x32 + softmax -------
__launch_bounds__(256)
__global__ void gates_kernel(const float* __restrict__ item, const int* __restrict__ seq,
                             float* __restrict__ out_gsm) {
    __shared__ float xs[8][512];
    int tid = threadIdx.x, w = tid >> 5, lane = tid & 31;
    int row = blockIdx.x * 8 + w;
    const float* xr = &item[(size_t)row * H_];
#pragma unroll
    for (int q = 0; q < 16; q++) xs[w][lane + q * 32] = xr[lane + q * 32];
    __syncwarp();
    float acc = 0.0f;
#pragma unroll 4
    for (int k = 0; k < H_; k++) acc += xs[w][k] * g_awT[k * A_ + lane];

    float mv = acc;
    int mi = lane;
    for (int o = 16; o; o >>= 1) {
        float ov = __shfl_xor_sync(0xffffffffu, mv, o);
        int oi = __shfl_xor_sync(0xffffffffu, mi, o);
        if (ov > mv || (ov == mv && oi < mi)) { mv = ov; mi = oi; }
    }
    float e = expf(acc - mv);
    float s = e;
    for (int o = 16; o; o >>= 1) s += __shfl_xor_sync(0xffffffffu, s, o);
    out_gsm[(size_t)row * A_ + lane] = e / s;
    g_bij[(size_t)row * A_ + lane] = acc;
    if (lane == 0 && seq[row] != 0) atomicAdd(&g_count[(row / S_) * A_ + mi], 1);
}

__global__ void mask_kernel(float* __restrict__ out_mask) {
    int i = blockIdx.x * blockDim.x + threadIdx.x;
    if (i < B_ * A_) out_mask[i] = (g_count[i] == 0) ? 1.0f : 0.0f;
}

// ---------------- routing: cijt = softmax(masked bij) * tma (exact) ------
__global__ void cijt_kernel(const int* __restrict__ seq) {
    int tid = threadIdx.x, w = tid >> 5, lane = tid & 31;
    int row = blockIdx.x * 8 + w;
    int b = row / S_;
    float v = (g_count[b * A_ + lane] == 0) ? NEGV : g_bij[row * A_ + lane];
    float mv = v;
    for (int o = 16; o; o >>= 1) mv = fmaxf(mv, __shfl_xor_sync(0xffffffffu, mv, o));
    float e = expf(v - mv);
    float s = e;
    for (int o = 16; o; o >>= 1) s += __shfl_xor_sync(0xffffffffu, s, o);
    float c = e / s;
    if (seq[row] == 0) c = 0.0f;
    g_cijt[row * A_ + lane] = c * g_w[row];
}

// ==== cap_tc: tf32 mma cap GEMM + fused squash. One CTA (256thr) per batch ==
#define CW_ST 40
#define MO_ST 520
#define CAP_ST 516
#define CAP_SMEMF (8000 + 12480 + 32)
__global__ void __launch_bounds__(256, 1) cap_tc(float* __restrict__ cap) {
    extern __shared__ float sm[];
    float* cw = sm;                        // [200][40]
    float* moed = sm + 8000;               // [3][8][520]
    float* capsm = sm;                     // overlay [32][516]
    float* scale = sm + 8000 + 12480;      // [32]
    const int b = blockIdx.x;
    const int tid = threadIdx.x, lane = tid & 31, wid = tid >> 5;
    const int g = lane >> 2, q = lane & 3;
    const int h0 = wid * 64;
    const uint32_t sbase = smem_u32(sm);

    auto issue = [&](int kc, int st) {
        const float* src = &g_moe[((size_t)b * S_ + kc * 8) * H_];
#pragma unroll
        for (int u = 0; u < 4; u++) {
            int un = tid + u * 256;
            int r = un >> 7, c4 = un & 127;
            CP_ASYNC16(sbase + (8000 + st * 8 * MO_ST + r * MO_ST + c4 * 4) * 4,
                       src + r * H_ + c4 * 4);
        }
    };
    issue(0, 0); CP_COMMIT();
    issue(1, 1); CP_COMMIT();

    {
        const float4* src = (const float4*)&g_cijt[(size_t)b * S_ * A_];
        for (int i = tid; i < S_ * 8; i += 256) {
            int s = i >> 3, c4 = i & 7;
            float4 v = src[i];
            cw[s * CW_ST + c4 * 4 + 0] = __uint_as_float(f2tf32(v.x));
            cw[s * CW_ST + c4 * 4 + 1] = __uint_as_float(f2tf32(v.y));
            cw[s * CW_ST + c4 * 4 + 2] = __uint_as_float(f2tf32(v.z));
            cw[s * CW_ST + c4 * 4 + 3] = __uint_as_float(f2tf32(v.w));
        }
    }

    float acc[2][8][4];
#pragma unroll
    for (int mi = 0; mi < 2; mi++)
#pragma unroll
        for (int ni = 0; ni < 8; ni++)
#pragma unroll
            for (int i = 0; i < 4; i++) acc[mi][ni][i] = 0.0f;

#pragma unroll 1
    for (int kc = 0; kc < 25; kc++) {
        if (kc + 2 < 25) issue(kc + 2, (kc + 2) % 3);
        CP_COMMIT();
        CP_WAIT2();
        __syncthreads();
        const float* mb = moed + (kc % 3) * 8 * MO_ST;
        uint32_t a0[2][4];
#pragma unroll
        for (int mi = 0; mi < 2; mi++) {
            a0[mi][0] = __float_as_uint(cw[(kc * 8 + q) * CW_ST + mi * 16 + g]);
            a0[mi][1] = __float_as_uint(cw[(kc * 8 + q) * CW_ST + mi * 16 + g + 8]);
            a0[mi][2] = __float_as_uint(cw[(kc * 8 + q + 4) * CW_ST + mi * 16 + g]);
            a0[mi][3] = __float_as_uint(cw[(kc * 8 + q + 4) * CW_ST + mi * 16 + g + 8]);
        }
#pragma unroll
        for (int ni = 0; ni < 8; ni++) {
            uint32_t b0 = f2tf32(mb[q * MO_ST + h0 + ni * 8 + g]);
            uint32_t b1 = f2tf32(mb[(q + 4) * MO_ST + h0 + ni * 8 + g]);
            mma_tf32(acc[0][ni], a0[0][0], a0[0][1], a0[0][2], a0[0][3], b0, b1);
            mma_tf32(acc[1][ni], a0[1][0], a0[1][1], a0[1][2], a0[1][3], b0, b1);
        }
        __syncthreads();
    }

    __syncthreads();
#pragma unroll
    for (int mi = 0; mi < 2; mi++)
#pragma unroll
        for (int ni = 0; ni < 8; ni++) {
            int cc = h0 + ni * 8 + 2 * q;
            capsm[(mi * 16 + g) * CAP_ST + cc]     = acc[mi][ni][0];
            capsm[(mi * 16 + g) * CAP_ST + cc + 1] = acc[mi][ni][1];
            capsm[(mi * 16 + g + 8) * CAP_ST + cc]     = acc[mi][ni][2];
            capsm[(mi * 16 + g + 8) * CAP_ST + cc + 1] = acc[mi][ni][3];
        }
    __syncthreads();
    {
        int a = tid >> 3, sub = tid & 7;
        float sq = 0.0f;
        const float* pr = &capsm[a * CAP_ST + sub * 64];
#pragma unroll 8
        for (int j = 0; j < 64; j++) sq += pr[j] * pr[j];
        sq += __shfl_xor_sync(0xffffffffu, sq, 1);
        sq += __shfl_xor_sync(0xffffffffu, sq, 2);
        sq += __shfl_xor_sync(0xffffffffu, sq, 4);
        if (sub == 0) scale[a] = sq / ((1.0f + sq) * sqrtf(sq + 1e-9f));
    }
    __syncthreads();
#pragma unroll 1
    for (int j = 0; j < 64; j++) {
        int i = tid + j * 256;
        int a = i >> 9, h = i & 511;
        cap[((size_t)b * A_ + a) * H_ + h] = capsm[a * CAP_ST + h] * scale[a];
    }
}

// ==== bij_tc: tf32 mma  bij[s][a] += moe[s,:] . cap[a,:]. One CTA per batch =
#define BMO_ST 40
#define BIJ_SMEMF (16512 + 20480)
__global__ void __launch_bounds__(256, 1) bij_tc(const float* __restrict__ cap) {
    extern __shared__ float sm[];
    float* capsm = sm;                       // [32][516]
    float* moesm = sm + 16512;               // [8][2][32][40]
    const int b = blockIdx.x;
    const int tid = threadIdx.x, lane = tid & 31, w = tid >> 5;
    const int g = lane >> 2, q = lane & 3;
    const uint32_t sbase = smem_u32(sm);

    {
        const float4* src = (const float4*)&cap[(size_t)b * A_ * H_];
        for (int j = 0; j < 16; j++) {
            int i = tid + j * 256;
            int a = i >> 7, c4 = i & 127;
            *(float4*)&capsm[a * CAP_ST + c4 * 4] = src[i];
        }
    }
    __syncthreads();

    float* msw = moesm + w * 2 * 32 * BMO_ST;
    const uint32_t mswb = sbase + (16512 + w * 2 * 32 * BMO_ST) * 4;
    const int row_base = w * 32;

    auto issue = [&](int kc, int st) {
#pragma unroll
        for (int j = 0; j < 8; j++) {
            int idx = lane + j * 32;
            int r = idx >> 3, c4 = idx & 7;
            int srow = row_base + r; if (srow > S_ - 1) srow = S_ - 1;
            CP_ASYNC16(mswb + (st * 32 * BMO_ST + r * BMO_ST + c4 * 4) * 4,
                       &g_moe[((size_t)b * S_ + srow) * H_ + kc * 32 + c4 * 4]);
        }
    };

    float acc[2][4][4];
#pragma unroll
    for (int mi = 0; mi < 2; mi++)
#pragma unroll
        for (int ni = 0; ni < 4; ni++)
#pragma unroll
            for (int i = 0; i < 4; i++) acc[mi][ni][i] = 0.0f;

    if (row_base < S_) {
        issue(0, 0); CP_COMMIT();
        issue(1, 1); CP_COMMIT();
#pragma unroll 1
        for (int kc = 0; kc < 16; kc++) {
            CP_WAIT1();
            __syncwarp();
            const float* ms = msw + (kc & 1) * 32 * BMO_ST;
#pragma unroll
            for (int ks = 0; ks < 4; ks++) {
                int k = ks * 8;
                uint32_t a0[2][4];
#pragma unroll
                for (int mi = 0; mi < 2; mi++) {
                    a0[mi][0] = f2tf32(ms[(mi * 16 + g) * BMO_ST + k + q]);
                    a0[mi][1] = f2tf32(ms[(mi * 16 + g + 8) * BMO_ST + k + q]);
                    a0[mi][2] = f2tf32(ms[(mi * 16 + g) * BMO_ST + k + q + 4]);
                    a0[mi][3] = f2tf32(ms[(mi * 16 + g + 8) * BMO_ST + k + q + 4]);
                }
                int K0 = kc * 32 + k;
#pragma unroll
                for (int ni = 0; ni < 4; ni++) {
                    uint32_t b0 = f2tf32(capsm[(ni * 8 + g) * CAP_ST + K0 + q]);
                    uint32_t b1 = f2tf32(capsm[(ni * 8 + g) * CAP_ST + K0 + q + 4]);
                    mma_tf32(acc[0][ni], a0[0][0], a0[0][1], a0[0][2], a0[0][3], b0, b1);
                    mma_tf32(acc[1][ni], a0[1][0], a0[1][1], a0[1][2], a0[1][3], b0, b1);
                }
            }
            __syncwarp();
            if (kc + 2 < 16) { issue(kc + 2, kc & 1); CP_COMMIT(); }
        }
#pragma unroll
        for (int mi = 0; mi < 2; mi++) {
            int r = row_base + mi * 16 + g;
#pragma unroll
            for (int ni = 0; ni < 4; ni++) {
                int cc = ni * 8 + 2 * q;
                if (r < S_) {
                    float2* p = (float2*)&g_bij[((size_t)b * S_ + r) * A_ + cc];
                    float2 v = *p; v.x += acc[mi][ni][0]; v.y += acc[mi][ni][1]; *p = v;
                }
                if (r + 8 < S_) {
                    float2* p = (float2*)&g_bij[((size_t)b * S_ + r + 8) * A_ + cc];
                    float2 v = *p; v.x += acc[mi][ni][2]; v.y += acc[mi][ni][3]; *p = v;
                }
            }
        }
    }
}

// ---------------- host ----------------
extern "C" void kernel_launch(void* const* d_in, const int* in_sizes, int n_in,
                              void* d_out, int out_size) {
    const float* item = (const float*)d_in[0];
    const int*   seq  = (const int*)d_in[1];
    const float* pos  = (const float*)d_in[2];
    const float* w1   = (const float*)d_in[3];
    const float* b1   = (const float*)d_in[4];
    const float* w2   = (const float*)d_in[5];
    // d_in[6] = attn_b2: softmax-invariant constant shift, a no-op
    const float* lw   = (const float*)d_in[7];
    const float* lb   = (const float*)d_in[8];
    const float* aw   = (const float*)d_in[9];
    const float* lng  = (const float*)d_in[10];
    const float* lnb  = (const float*)d_in[11];

    const size_t CAPN = (size_t)B_ * A_ * H_;
    const size_t GSN  = (size_t)M_ * A_;
    const size_t MKN  = (size_t)B_ * A_;

    float* out_cap = (float*)d_out;
    float* out_gsm;
    float* out_mask;
    if ((size_t)out_size >= CAPN + GSN + MKN) {
        out_gsm  = out_cap + CAPN;
        out_mask = out_cap + CAPN + GSN;
    } else {
        void* p;
        cudaGetSymbolAddress(&p, g_dummy_gates); out_gsm = (float*)p;
        cudaGetSymbolAddress(&p, g_dummy_mask);  out_mask = (float*)p;
    }

    cudaFuncSetAttribute(gemm10<0>, cudaFuncAttributeMaxDynamicSharedMemorySize, SMEM_G);
    cudaFuncSetAttribute(gemm10<1>, cudaFuncAttributeMaxDynamicSharedMemorySize, SMEM_G);
    cudaFuncSetAttribute(cap_tc, cudaFuncAttributeMaxDynamicSharedMemorySize, CAP_SMEMF * 4);
    cudaFuncSetAttribute(bij_tc, cudaFuncAttributeMaxDynamicSharedMemorySize, BIJ_SMEMF * 4);

    __nv_bfloat16 *a0h, *a0l, *a1h;
    { void* p;
      cudaGetSymbolAddress(&p, g_A0h); a0h = (__nv_bfloat16*)p;
      cudaGetSymbolAddress(&p, g_A0l); a0l = (__nv_bfloat16*)p;
      cudaGetSymbolAddress(&p, g_A1h); a1h = (__nv_bfloat16*)p; }

    // side stream + fork/join events (capture-legal fork-join pattern)
    cudaStream_t s2;
    cudaStreamCreateWithFlags(&s2, cudaStreamNonBlocking);
    cudaEvent_t evFork, evJoin;
    cudaEventCreateWithFlags(&evFork, cudaEventDisableTiming);
    cudaEventCreateWithFlags(&evJoin, cudaEventDisableTiming);

    // main: prep -> zero -> [fork] -> tw(w1) -> gemm0 (4th launch, ncu slot)
    prep_kernel<<<(M_ * H_ / 4 + 255) / 256, 256>>>(item, pos);
    zero_kernel<<<(M_ + 255) / 256, 256>>>();
    cudaEventRecord(evFork, 0);
    transpose_w_kernel<<<256, 256>>>(w1);
    gemm10<0><<<dim3(4, 400), 512, SMEM_G>>>(a0h, a0l, item, b1, w2);

    // side: gates chain overlaps gemm0/gemm1 (depends only on inputs + zero)
    cudaStreamWaitEvent(s2, evFork, 0);
    transpose_aw_kernel<<<(A_ * H_ + 255) / 256, 256, 0, s2>>>(aw);
    gates_kernel<<<M_ / 8, 256, 0, s2>>>(item, seq, out_gsm);
    mask_kernel<<<(B_ * A_ + 255) / 256, 256, 0, s2>>>(out_mask);
    cudaEventRecord(evJoin, s2);

    // main continues
    tma_softmax_kernel<<<B_, 256>>>(seq);
    transpose_w_kernel<<<256, 256>>>(lw);
    gemm10<1><<<dim3(4, 400), 512, SMEM_G>>>(a1h, a1h, item, lb, nullptr);
    ln_kernel<<<M_ / 8, 256>>>(lng, lnb);

    // join: routing needs g_bij/g_count from the gates chain
    cudaStreamWaitEvent(0, evJoin, 0);
    for (int t = 0; t < 3; t++) {
        cijt_kernel<<<M_ / 8, 256>>>(seq);
        cap_tc<<<B_, 256, CAP_SMEMF * 4>>>(out_cap);
        if (t < 2) bij_tc<<<B_, 256, BIJ_SMEMF * 4>>>(out_cap);
    }
}